// round 1
// baseline (speedup 1.0000x reference)
#include <cuda_runtime.h>

// ---------------------------------------------------------------------------
// EncoderByType: 3 per-type MLPs (Linear+Sigmoid x3), node_type sorted
//   type0: 100000 rows, d_in= 64
//   type1:  80000 rows, d_in=128
//   type2:  60000 rows, d_in=256
// hidden 512 -> 512 -> 256, sigmoid after EVERY layer.
// Output rows are contiguous per type (bases 0 / n0 / n0+n1).
// Round 1: fp32 tiled SGEMM fused with bias+sigmoid. 9 launches.
// ---------------------------------------------------------------------------

#define BM 128
#define BN 128
#define BK 8
#define PAD 4

// Scratch for hidden activations (allocation-free: __device__ globals).
// 240000 * 512 floats = 491.5 MB each.
__device__ float g_h1[240000ull * 512];
__device__ float g_h2[240000ull * 512];

__device__ __forceinline__ float sigmoidf_fast(float z) {
    return 1.0f / (1.0f + __expf(-z));
}

// C[M,N] = sigmoid(A[M,K] @ W[K,N] + bias[N])
// A/C selected by sel: 0=external ptr, 1=g_h1, 2=g_h2 (plus element offset).
// Requires: K % 8 == 0, N % 128 == 0. M arbitrary (bounds-checked).
__global__ void __launch_bounds__(256, 2)
gemm_bias_sigmoid(const float* __restrict__ Aext, int Asel, long long Aoff,
                  const float* __restrict__ W, const float* __restrict__ bias,
                  float* __restrict__ Cext, int Csel, long long Coff,
                  int M, int K, int N)
{
    const float* A =
        (Asel == 0 ? Aext : (Asel == 1 ? (const float*)g_h1 : (const float*)g_h2)) + Aoff;
    float* C =
        (Csel == 0 ? Cext : (Csel == 1 ? g_h1 : g_h2)) + Coff;

    __shared__ float As[BK][BM + PAD];   // transposed A tile, padded (row=528B, 16B-aligned)
    __shared__ float Bs[BK][BN];

    const int tid = threadIdx.x;
    const int bm = blockIdx.y * BM;
    const int bn = blockIdx.x * BN;

    const int tx = tid & 15;   // 16 thread-cols
    const int ty = tid >> 4;   // 16 thread-rows

    // A-tile load map: 128x8 floats = 256 float4s; thread t -> row t/2, col (t&1)*4
    const int ar = tid >> 1;
    const int ac = (tid & 1) * 4;
    // B-tile load map: 8x128 floats = 256 float4s; thread t -> row t/32, col (t&31)*4
    const int br = tid >> 5;
    const int bc = (tid & 31) * 4;

    float acc[8][8];
#pragma unroll
    for (int i = 0; i < 8; i++)
#pragma unroll
        for (int j = 0; j < 8; j++) acc[i][j] = 0.0f;

    const int arow = bm + ar;
    const bool arow_ok = (arow < M);
    const float* Aptr = A + (long long)arow * K + ac;
    const float* Wptr = W + (long long)br * N + bn + bc;

    for (int k0 = 0; k0 < K; k0 += BK) {
        // --- load A tile (transposed into smem) ---
        float4 av = make_float4(0.f, 0.f, 0.f, 0.f);
        if (arow_ok)
            av = *reinterpret_cast<const float4*>(Aptr + k0);
        As[ac + 0][ar] = av.x;
        As[ac + 1][ar] = av.y;
        As[ac + 2][ar] = av.z;
        As[ac + 3][ar] = av.w;
        // --- load B tile ---
        float4 bv = *reinterpret_cast<const float4*>(Wptr + (long long)k0 * N);
        *reinterpret_cast<float4*>(&Bs[br][bc]) = bv;
        __syncthreads();

#pragma unroll
        for (int k = 0; k < BK; k++) {
            float a[8], b[8];
            float4 a0 = *reinterpret_cast<const float4*>(&As[k][ty * 8]);
            float4 a1 = *reinterpret_cast<const float4*>(&As[k][ty * 8 + 4]);
            float4 b0 = *reinterpret_cast<const float4*>(&Bs[k][tx * 8]);
            float4 b1 = *reinterpret_cast<const float4*>(&Bs[k][tx * 8 + 4]);
            a[0] = a0.x; a[1] = a0.y; a[2] = a0.z; a[3] = a0.w;
            a[4] = a1.x; a[5] = a1.y; a[6] = a1.z; a[7] = a1.w;
            b[0] = b0.x; b[1] = b0.y; b[2] = b0.z; b[3] = b0.w;
            b[4] = b1.x; b[5] = b1.y; b[6] = b1.z; b[7] = b1.w;
#pragma unroll
            for (int i = 0; i < 8; i++)
#pragma unroll
                for (int j = 0; j < 8; j++)
                    acc[i][j] = fmaf(a[i], b[j], acc[i][j]);
        }
        __syncthreads();
    }

    // --- epilogue: bias + sigmoid, vectorized stores ---
    float bias_r[8];
#pragma unroll
    for (int j = 0; j < 8; j++) bias_r[j] = bias[bn + tx * 8 + j];

#pragma unroll
    for (int i = 0; i < 8; i++) {
        int row = bm + ty * 8 + i;
        if (row < M) {
            float4 o0, o1;
            o0.x = sigmoidf_fast(acc[i][0] + bias_r[0]);
            o0.y = sigmoidf_fast(acc[i][1] + bias_r[1]);
            o0.z = sigmoidf_fast(acc[i][2] + bias_r[2]);
            o0.w = sigmoidf_fast(acc[i][3] + bias_r[3]);
            o1.x = sigmoidf_fast(acc[i][4] + bias_r[4]);
            o1.y = sigmoidf_fast(acc[i][5] + bias_r[5]);
            o1.z = sigmoidf_fast(acc[i][6] + bias_r[6]);
            o1.w = sigmoidf_fast(acc[i][7] + bias_r[7]);
            float* cp = C + (long long)row * N + bn + tx * 8;
            *reinterpret_cast<float4*>(cp) = o0;
            *reinterpret_cast<float4*>(cp + 4) = o1;
        }
    }
}

extern "C" void kernel_launch(void* const* d_in, const int* in_sizes, int n_in,
                              void* d_out, int out_size)
{
    (void)n_in; (void)out_size;
    const int din[3] = {64, 128, 256};
    int n[3];
    for (int t = 0; t < 3; t++) n[t] = in_sizes[t] / din[t];
    long long base[3] = {0, n[0], (long long)n[0] + n[1]};

    float* out = (float*)d_out;

    for (int t = 0; t < 3; t++) {
        const float* x  = (const float*)d_in[t];
        const float* W1 = (const float*)d_in[4 + 6 * t];
        const float* b1 = (const float*)d_in[5 + 6 * t];
        const float* W2 = (const float*)d_in[6 + 6 * t];
        const float* b2 = (const float*)d_in[7 + 6 * t];
        const float* W3 = (const float*)d_in[8 + 6 * t];
        const float* b3 = (const float*)d_in[9 + 6 * t];

        const int M = n[t];
        const int K = din[t];
        dim3 block(256);
        dim3 g12(512 / BN, (M + BM - 1) / BM);
        dim3 g3 (256 / BN, (M + BM - 1) / BM);

        // layer 1: x[M,K] -> h1[M,512]
        gemm_bias_sigmoid<<<g12, block>>>(x, 0, 0,
                                          W1, b1,
                                          nullptr, 1, base[t] * 512,
                                          M, K, 512);
        // layer 2: h1[M,512] -> h2[M,512]
        gemm_bias_sigmoid<<<g12, block>>>(nullptr, 1, base[t] * 512,
                                          W2, b2,
                                          nullptr, 2, base[t] * 512,
                                          M, 512, 512);
        // layer 3: h2[M,512] -> out[M,256]
        gemm_bias_sigmoid<<<g3, block>>>(nullptr, 2, base[t] * 512,
                                         W3, b3,
                                         out, 0, base[t] * 256,
                                         M, 512, 256);
    }
}

// round 2
// speedup vs baseline: 1.0004x; 1.0004x over previous
#include <cuda_runtime.h>

// ---------------------------------------------------------------------------
// EncoderByType: 3 per-type MLPs (Linear+Sigmoid x3), node_type sorted
//   type0: 100000 rows, d_in= 64
//   type1:  80000 rows, d_in=128
//   type2:  60000 rows, d_in=256
// hidden 512 -> 512 -> 256, sigmoid after EVERY layer.
// Output rows are contiguous per type (bases 0 / n0 / n0+n1).
// Round 1: fp32 tiled SGEMM fused with bias+sigmoid. 9 launches.
// ---------------------------------------------------------------------------

#define BM 128
#define BN 128
#define BK 8
#define PAD 4

// Scratch for hidden activations (allocation-free: __device__ globals).
// 240000 * 512 floats = 491.5 MB each.
__device__ float g_h1[240000ull * 512];
__device__ float g_h2[240000ull * 512];

__device__ __forceinline__ float sigmoidf_fast(float z) {
    return 1.0f / (1.0f + __expf(-z));
}

// C[M,N] = sigmoid(A[M,K] @ W[K,N] + bias[N])
// A/C selected by sel: 0=external ptr, 1=g_h1, 2=g_h2 (plus element offset).
// Requires: K % 8 == 0, N % 128 == 0. M arbitrary (bounds-checked).
__global__ void __launch_bounds__(256, 2)
gemm_bias_sigmoid(const float* __restrict__ Aext, int Asel, long long Aoff,
                  const float* __restrict__ W, const float* __restrict__ bias,
                  float* __restrict__ Cext, int Csel, long long Coff,
                  int M, int K, int N)
{
    const float* A =
        (Asel == 0 ? Aext : (Asel == 1 ? (const float*)g_h1 : (const float*)g_h2)) + Aoff;
    float* C =
        (Csel == 0 ? Cext : (Csel == 1 ? g_h1 : g_h2)) + Coff;

    __shared__ float As[BK][BM + PAD];   // transposed A tile, padded (row=528B, 16B-aligned)
    __shared__ float Bs[BK][BN];

    const int tid = threadIdx.x;
    const int bm = blockIdx.y * BM;
    const int bn = blockIdx.x * BN;

    const int tx = tid & 15;   // 16 thread-cols
    const int ty = tid >> 4;   // 16 thread-rows

    // A-tile load map: 128x8 floats = 256 float4s; thread t -> row t/2, col (t&1)*4
    const int ar = tid >> 1;
    const int ac = (tid & 1) * 4;
    // B-tile load map: 8x128 floats = 256 float4s; thread t -> row t/32, col (t&31)*4
    const int br = tid >> 5;
    const int bc = (tid & 31) * 4;

    float acc[8][8];
#pragma unroll
    for (int i = 0; i < 8; i++)
#pragma unroll
        for (int j = 0; j < 8; j++) acc[i][j] = 0.0f;

    const int arow = bm + ar;
    const bool arow_ok = (arow < M);
    const float* Aptr = A + (long long)arow * K + ac;
    const float* Wptr = W + (long long)br * N + bn + bc;

    for (int k0 = 0; k0 < K; k0 += BK) {
        // --- load A tile (transposed into smem) ---
        float4 av = make_float4(0.f, 0.f, 0.f, 0.f);
        if (arow_ok)
            av = *reinterpret_cast<const float4*>(Aptr + k0);
        As[ac + 0][ar] = av.x;
        As[ac + 1][ar] = av.y;
        As[ac + 2][ar] = av.z;
        As[ac + 3][ar] = av.w;
        // --- load B tile ---
        float4 bv = *reinterpret_cast<const float4*>(Wptr + (long long)k0 * N);
        *reinterpret_cast<float4*>(&Bs[br][bc]) = bv;
        __syncthreads();

#pragma unroll
        for (int k = 0; k < BK; k++) {
            float a[8], b[8];
            float4 a0 = *reinterpret_cast<const float4*>(&As[k][ty * 8]);
            float4 a1 = *reinterpret_cast<const float4*>(&As[k][ty * 8 + 4]);
            float4 b0 = *reinterpret_cast<const float4*>(&Bs[k][tx * 8]);
            float4 b1 = *reinterpret_cast<const float4*>(&Bs[k][tx * 8 + 4]);
            a[0] = a0.x; a[1] = a0.y; a[2] = a0.z; a[3] = a0.w;
            a[4] = a1.x; a[5] = a1.y; a[6] = a1.z; a[7] = a1.w;
            b[0] = b0.x; b[1] = b0.y; b[2] = b0.z; b[3] = b0.w;
            b[4] = b1.x; b[5] = b1.y; b[6] = b1.z; b[7] = b1.w;
#pragma unroll
            for (int i = 0; i < 8; i++)
#pragma unroll
                for (int j = 0; j < 8; j++)
                    acc[i][j] = fmaf(a[i], b[j], acc[i][j]);
        }
        __syncthreads();
    }

    // --- epilogue: bias + sigmoid, vectorized stores ---
    float bias_r[8];
#pragma unroll
    for (int j = 0; j < 8; j++) bias_r[j] = bias[bn + tx * 8 + j];

#pragma unroll
    for (int i = 0; i < 8; i++) {
        int row = bm + ty * 8 + i;
        if (row < M) {
            float4 o0, o1;
            o0.x = sigmoidf_fast(acc[i][0] + bias_r[0]);
            o0.y = sigmoidf_fast(acc[i][1] + bias_r[1]);
            o0.z = sigmoidf_fast(acc[i][2] + bias_r[2]);
            o0.w = sigmoidf_fast(acc[i][3] + bias_r[3]);
            o1.x = sigmoidf_fast(acc[i][4] + bias_r[4]);
            o1.y = sigmoidf_fast(acc[i][5] + bias_r[5]);
            o1.z = sigmoidf_fast(acc[i][6] + bias_r[6]);
            o1.w = sigmoidf_fast(acc[i][7] + bias_r[7]);
            float* cp = C + (long long)row * N + bn + tx * 8;
            *reinterpret_cast<float4*>(cp) = o0;
            *reinterpret_cast<float4*>(cp + 4) = o1;
        }
    }
}

extern "C" void kernel_launch(void* const* d_in, const int* in_sizes, int n_in,
                              void* d_out, int out_size)
{
    (void)n_in; (void)out_size;
    const int din[3] = {64, 128, 256};
    int n[3];
    for (int t = 0; t < 3; t++) n[t] = in_sizes[t] / din[t];
    long long base[3] = {0, n[0], (long long)n[0] + n[1]};

    float* out = (float*)d_out;

    for (int t = 0; t < 3; t++) {
        const float* x  = (const float*)d_in[t];
        const float* W1 = (const float*)d_in[4 + 6 * t];
        const float* b1 = (const float*)d_in[5 + 6 * t];
        const float* W2 = (const float*)d_in[6 + 6 * t];
        const float* b2 = (const float*)d_in[7 + 6 * t];
        const float* W3 = (const float*)d_in[8 + 6 * t];
        const float* b3 = (const float*)d_in[9 + 6 * t];

        const int M = n[t];
        const int K = din[t];
        dim3 block(256);
        dim3 g12(512 / BN, (M + BM - 1) / BM);
        dim3 g3 (256 / BN, (M + BM - 1) / BM);

        // layer 1: x[M,K] -> h1[M,512]
        gemm_bias_sigmoid<<<g12, block>>>(x, 0, 0,
                                          W1, b1,
                                          nullptr, 1, base[t] * 512,
                                          M, K, 512);
        // layer 2: h1[M,512] -> h2[M,512]
        gemm_bias_sigmoid<<<g12, block>>>(nullptr, 1, base[t] * 512,
                                          W2, b2,
                                          nullptr, 2, base[t] * 512,
                                          M, 512, 512);
        // layer 3: h2[M,512] -> out[M,256]
        gemm_bias_sigmoid<<<g3, block>>>(nullptr, 2, base[t] * 512,
                                         W3, b3,
                                         out, 0, base[t] * 256,
                                         M, 512, 256);
    }
}

// round 5
// speedup vs baseline: 1.7834x; 1.7827x over previous
#include <cuda_runtime.h>
#include <cstdint>

// ---------------------------------------------------------------------------
// EncoderByType on GB300 (compiled as compute_103 baseline -> no tcgen05).
// Round 3: legacy mma.sync tf32 (m16n8k8) tiled GEMM fused with bias+sigmoid.
//   CTA tile 128x128x32, 8 warps (warp tile 32x64), double-buffered smem,
//   pre-paired float4 fragment layout => all LDS are conflict-free LDS.128.
// Weights pre-transposed to [N,K] once per launch.
// ---------------------------------------------------------------------------

__device__ float g_h1[240000ull * 512];
__device__ float g_h2[240000ull * 512];
__device__ float g_Wt[1409024];   // 9 weight matrices, [N,K] layout

__device__ __forceinline__ float cvt_tf32(float x) {
    float y;
    asm("cvt.rna.tf32.f32 %0, %1;" : "=f"(y) : "f"(x));
    return y;
}

__device__ __forceinline__ void mma_tf32(float* d, const float4& a,
                                         float b0, float b1) {
    asm volatile(
        "mma.sync.aligned.m16n8k8.row.col.f32.tf32.tf32.f32 "
        "{%0,%1,%2,%3}, {%4,%5,%6,%7}, {%8,%9}, {%0,%1,%2,%3};"
        : "+f"(d[0]), "+f"(d[1]), "+f"(d[2]), "+f"(d[3])
        : "r"(__float_as_uint(a.x)), "r"(__float_as_uint(a.y)),
          "r"(__float_as_uint(a.z)), "r"(__float_as_uint(a.w)),
          "r"(__float_as_uint(b0)), "r"(__float_as_uint(b1)));
}

// ------------------------- weight transpose --------------------------------
struct TransArgs {
    const float* W[9];
    long long wtoff[9];
    int K[9];
    int N[9];
    int tbase[10];
};

__global__ void __launch_bounds__(256)
transpose_weights(TransArgs a) {
    int m = 0;
    while ((int)blockIdx.x >= a.tbase[m + 1]) m++;
    int t = blockIdx.x - a.tbase[m];
    int Km = a.K[m], Nm = a.N[m];
    int tilesN = Nm >> 5;
    int tk = t / tilesN, tn = t % tilesN;

    __shared__ float tile[32][33];
    int tx = threadIdx.x & 31, ty0 = threadIdx.x >> 5;
    const float* W = a.W[m];
#pragma unroll
    for (int i = 0; i < 4; i++) {
        int ty = ty0 + i * 8;
        tile[ty][tx] = W[(long long)(tk * 32 + ty) * Nm + tn * 32 + tx];
    }
    __syncthreads();
    float* Wt = g_Wt + a.wtoff[m];
#pragma unroll
    for (int i = 0; i < 4; i++) {
        int ty = ty0 + i * 8;
        Wt[(long long)(tn * 32 + ty) * Km + tk * 32 + tx] = tile[tx][ty];
    }
}

// ------------------------- fused MMA GEMM ----------------------------------
// C[M,N] = sigmoid(A[M,K] @ W[K,N] + bias), Wt is [N,K].
// Grid: (N/128, ceil(M/128)). Block 256 = 8 warps, warp grid 4(m) x 2(n).
// Smem per buffer: A 16KB + B 16KB as paired float4 fragments:
//   f4 at index ((s*8+mp)*8+g)*4+c  =  {X[r][k], X[r+8][k], X[r][k+4], X[r+8][k+4]}
//   with r = mp*16+g, k = s*8+c   (s: k8-step 0..3, mp: 16-row group 0..7).
__global__ void __launch_bounds__(256, 2)
mlp_mma_tf32(const float* __restrict__ Aext, int Asel, long long Aoff,
             long long WtOff, const float* __restrict__ bias,
             float* __restrict__ Cext, int Csel, long long Coff,
             int M, int K, int N)
{
    extern __shared__ float4 sm4[];   // [2][2048]: buf -> A(1024 f4) then B(1024 f4)
    const float* A =
        (Asel == 0 ? Aext : (Asel == 1 ? (const float*)g_h1 : (const float*)g_h2)) + Aoff;
    float* C = (Csel == 0 ? Cext : (Csel == 1 ? g_h1 : g_h2)) + Coff;
    const float* Wt = g_Wt + WtOff;

    const int tid = threadIdx.x;
    const int wid = tid >> 5;
    const int lane = tid & 31;
    const int g = lane >> 2;       // 0..7
    const int c = lane & 3;        // 0..3
    const int warp_m = wid & 3;    // 4 m-warps (32 rows each)
    const int warp_n = wid >> 2;   // 2 n-warps (64 cols each)

    const long long bm = (long long)blockIdx.y * 128;
    const int bn = blockIdx.x * 128;
    const int KT = K >> 5;

    float acc[2][4][2][4];   // [mt][np][half][4]
#pragma unroll
    for (int i = 0; i < 2; i++)
#pragma unroll
        for (int j = 0; j < 4; j++)
#pragma unroll
            for (int h = 0; h < 2; h++)
#pragma unroll
                for (int q = 0; q < 4; q++) acc[i][j][h][q] = 0.0f;

    // ---------- staging helper (p = wid*4+i enumerates the 32 (s,mp) units) --
    auto stage = [&](int kt, int buf) {
        float4* As = sm4 + buf * 2048;
        float4* Bs = As + 1024;
#pragma unroll
        for (int i = 0; i < 4; i++) {
            const int p = wid * 4 + i;          // p = s*8 + mp
            const int s = p >> 3, mp = p & 7;
            const int r = mp * 16 + g;
            const int kk = kt * 32 + s * 8 + c;
            // A: rows bm+r, bm+r+8 (guarded)
            long long r0 = bm + r, r1 = bm + r + 8;
            float v0 = 0.f, v1 = 0.f, v2 = 0.f, v3 = 0.f;
            if (r0 < M) { v0 = A[r0 * K + kk]; v2 = A[r0 * K + kk + 4]; }
            if (r1 < M) { v1 = A[r1 * K + kk]; v3 = A[r1 * K + kk + 4]; }
            As[(p * 8 + g) * 4 + c] =
                make_float4(cvt_tf32(v0), cvt_tf32(v1), cvt_tf32(v2), cvt_tf32(v3));
            // B: rows bn+r, bn+r+8 of Wt[N,K] (always in-bounds)
            const float* w0 = Wt + (long long)(bn + r) * K + kk;
            const float* w1 = w0 + 8ll * K;
            Bs[(p * 8 + g) * 4 + c] =
                make_float4(cvt_tf32(w0[0]), cvt_tf32(w1[0]),
                            cvt_tf32(w0[4]), cvt_tf32(w1[4]));
        }
    };

    stage(0, 0);
    __syncthreads();

    for (int kt = 0; kt < KT; kt++) {
        const int buf = kt & 1;
        const float4* As = sm4 + buf * 2048;
        const float4* Bs = As + 1024;
#pragma unroll
        for (int s = 0; s < 4; s++) {
            float4 af[2];
#pragma unroll
            for (int mt = 0; mt < 2; mt++)
                af[mt] = As[((s * 8 + (warp_m * 2 + mt)) * 8 + g) * 4 + c];
            float4 bf[4];
#pragma unroll
            for (int np = 0; np < 4; np++)
                bf[np] = Bs[((s * 8 + (warp_n * 4 + np)) * 8 + g) * 4 + c];
#pragma unroll
            for (int mt = 0; mt < 2; mt++)
#pragma unroll
                for (int np = 0; np < 4; np++) {
                    mma_tf32(acc[mt][np][0], af[mt], bf[np].x, bf[np].z);
                    mma_tf32(acc[mt][np][1], af[mt], bf[np].y, bf[np].w);
                }
        }
        if (kt + 1 < KT) {
            stage(kt + 1, buf ^ 1);
            __syncthreads();
        }
    }

    // ---------- epilogue: bias + sigmoid ------------------------------------
#pragma unroll
    for (int mt = 0; mt < 2; mt++) {
        long long row0 = bm + warp_m * 32 + mt * 16 + g;
        long long row1 = row0 + 8;
#pragma unroll
        for (int np = 0; np < 4; np++)
#pragma unroll
            for (int h = 0; h < 2; h++) {
                int n = bn + warp_n * 64 + np * 16 + h * 8 + 2 * c;
                float b0 = bias[n], b1 = bias[n + 1];
                float* d = acc[mt][np][h];
                if (row0 < M) {
                    float2 o;
                    o.x = 1.0f / (1.0f + __expf(-(d[0] + b0)));
                    o.y = 1.0f / (1.0f + __expf(-(d[1] + b1)));
                    *(float2*)(C + row0 * N + n) = o;
                }
                if (row1 < M) {
                    float2 o;
                    o.x = 1.0f / (1.0f + __expf(-(d[2] + b0)));
                    o.y = 1.0f / (1.0f + __expf(-(d[3] + b1)));
                    *(float2*)(C + row1 * N + n) = o;
                }
            }
    }
}

// ------------------------- host launcher -----------------------------------
extern "C" void kernel_launch(void* const* d_in, const int* in_sizes, int n_in,
                              void* d_out, int out_size)
{
    (void)n_in; (void)out_size;
    const int din[3] = {64, 128, 256};
    int n[3];
    for (int t = 0; t < 3; t++) n[t] = in_sizes[t] / din[t];
    long long base[3] = {0, n[0], (long long)n[0] + n[1]};
    float* out = (float*)d_out;

    const int SMEM = 2 * 2048 * 16;   // 65536 bytes
    static int attr_done = 0;
    if (!attr_done) {
        cudaFuncSetAttribute(mlp_mma_tf32,
                             cudaFuncAttributeMaxDynamicSharedMemorySize, SMEM);
        attr_done = 1;
    }

    // ---- transpose all weights into g_Wt ([N,K]) ----
    TransArgs ta;
    long long woff[9];
    {
        long long w = 0;
        int tb = 0;
        for (int t = 0; t < 3; t++) {
            int Ks[3] = {din[t], 512, 512};
            int Ns[3] = {512, 512, 256};
            for (int l = 0; l < 3; l++) {
                int idx = t * 3 + l;
                ta.W[idx] = (const float*)d_in[4 + 6 * t + 2 * l];
                ta.wtoff[idx] = w;
                woff[idx] = w;
                ta.K[idx] = Ks[l];
                ta.N[idx] = Ns[l];
                ta.tbase[idx] = tb;
                tb += (Ks[l] / 32) * (Ns[l] / 32);
                w += (long long)Ks[l] * Ns[l];
            }
        }
        ta.tbase[9] = tb;
        transpose_weights<<<tb, 256>>>(ta);
    }

    for (int t = 0; t < 3; t++) {
        const float* x  = (const float*)d_in[t];
        const float* b1 = (const float*)d_in[5 + 6 * t];
        const float* b2 = (const float*)d_in[7 + 6 * t];
        const float* b3 = (const float*)d_in[9 + 6 * t];
        const int M = n[t];
        const int gy = (M + 127) / 128;

        dim3 g512(4, gy), g256(2, gy), blk(256);

        mlp_mma_tf32<<<g512, blk, SMEM>>>(x, 0, 0,
                                          woff[t * 3 + 0], b1,
                                          nullptr, 1, base[t] * 512,
                                          M, din[t], 512);
        mlp_mma_tf32<<<g512, blk, SMEM>>>(nullptr, 1, base[t] * 512,
                                          woff[t * 3 + 1], b2,
                                          nullptr, 2, base[t] * 512,
                                          M, 512, 512);
        mlp_mma_tf32<<<g256, blk, SMEM>>>(nullptr, 2, base[t] * 512,
                                          woff[t * 3 + 2], b3,
                                          out, 0, base[t] * 256,
                                          M, 512, 256);
    }
}

// round 6
// speedup vs baseline: 4.1018x; 2.3000x over previous
#include <cuda_runtime.h>
#include <cuda_fp16.h>
#include <cstdint>

// ---------------------------------------------------------------------------
// EncoderByType (GB300, compute_103 baseline -> legacy mma.sync path).
// Round 6: fp16 m16n8k16 MMA (same mantissa as tf32, 2x rate, 1/2 smem bytes),
// CTA tile 256x128, warp tile 64x64, register-prefetch + double-buffered smem,
// fp16 intermediate activations, 3 merged layer launches + 1 weight transpose.
// ---------------------------------------------------------------------------

// scratch (allocation-free): padded to 256-row tiles per type
__device__ __half g_h1[245760ll * 512];
__device__ __half g_h2[245760ll * 512];
__device__ __half g_Wt[1409024];          // 9 weight matrices, [N,K] fp16

// ------------------------- device helpers ----------------------------------
__device__ __forceinline__ float fast_sigmoid(float x) {
    float t;
    asm("tanh.approx.f32 %0, %1;" : "=f"(t) : "f"(0.5f * x));
    return fmaf(0.5f, t, 0.5f);
}

__device__ __forceinline__ void mma_fp16(float* d, const uint4& a,
                                         uint32_t b0, uint32_t b1) {
    asm volatile(
        "mma.sync.aligned.m16n8k16.row.col.f32.f16.f16.f32 "
        "{%0,%1,%2,%3}, {%4,%5,%6,%7}, {%8,%9}, {%0,%1,%2,%3};"
        : "+f"(d[0]), "+f"(d[1]), "+f"(d[2]), "+f"(d[3])
        : "r"(a.x), "r"(a.y), "r"(a.z), "r"(a.w), "r"(b0), "r"(b1));
}

__device__ __forceinline__ uint32_t packh2(float lo, float hi) {
    __half2 h = __floats2half2_rn(lo, hi);
    return *reinterpret_cast<uint32_t*>(&h);
}

// ------------------------- weight transpose+convert ------------------------
struct TransArgs {
    const float* W[9];
    long long wtoff[9];
    int K[9];
    int N[9];
    int tbase[10];
};

__global__ void __launch_bounds__(256)
transpose_weights(TransArgs a) {
    int m = 0;
    while ((int)blockIdx.x >= a.tbase[m + 1]) m++;
    int t = blockIdx.x - a.tbase[m];
    int Km = a.K[m], Nm = a.N[m];
    int tilesN = Nm >> 5;
    int tk = t / tilesN, tn = t % tilesN;

    __shared__ float tile[32][33];
    int tx = threadIdx.x & 31, ty0 = threadIdx.x >> 5;
    const float* W = a.W[m];
#pragma unroll
    for (int i = 0; i < 4; i++) {
        int ty = ty0 + i * 8;
        tile[ty][tx] = W[(long long)(tk * 32 + ty) * Nm + tn * 32 + tx];
    }
    __syncthreads();
    __half* Wt = g_Wt + a.wtoff[m];
#pragma unroll
    for (int i = 0; i < 4; i++) {
        int ty = ty0 + i * 8;
        Wt[(long long)(tn * 32 + ty) * Km + tk * 32 + tx] = __float2half(tile[tx][ty]);
    }
}

// ------------------------- fused layer kernel ------------------------------
// One launch handles all 3 types of one layer. Grid: (N/128, sum_tiles).
// CTA tile 256(m) x 128(n), 8 warps = 4(m) x 2(n), warp tile 64 x 64.
// Smem fragment layout (per buffer): A 1024 uint4 then B 512 uint4.
//   A f4 idx ((s*16+mp)*8+g)*4+c = full m16n8k16 A-fragment {a0,a1,a2,a3}
//     for 16-row group mp, k16-step s.  B f4 idx ((s*8+npr)*8+g)*4+c =
//     {b0,b1} for two adjacent n8 tiles of 16-col group npr.
struct LArgs {
    const void* A[3];
    void* C[3];
    const float* bias[3];
    long long wt[3];
    int M[3], K[3];
    int tb[4];
    int N;
};

template <bool AF32, bool CF32>
__global__ void __launch_bounds__(256, 1)
mlp_layer(LArgs a)
{
    extern __shared__ uint4 sm[];   // [2][1536]
    const int t = ((int)blockIdx.y >= a.tb[1]) + ((int)blockIdx.y >= a.tb[2]);
    const int M = a.M[t];
    const int K = a.K[t];
    const int N = a.N;
    const long long bm = (long long)((int)blockIdx.y - a.tb[t]) * 256;
    const int bn = blockIdx.x * 128;
    const char* Ab = (const char*)a.A[t];
    const __half* Wt = g_Wt + a.wt[t];
    const float* bias = a.bias[t];

    const int tid = threadIdx.x;
    const int wid = tid >> 5;
    const int lane = tid & 31;
    const int g = lane >> 2;
    const int c = lane & 3;
    const int warp_m = wid & 3;
    const int warp_n = wid >> 2;
    const int KT = K >> 5;
    const int ES = AF32 ? 4 : 2;

    // ---- gather pointers (advance by 32*ES bytes per k-slab) ----
    const char* pa0[4];
    const char* pa1[4];
#pragma unroll
    for (int i = 0; i < 4; i++) {
        int idx = tid + i * 256;
        int cc = idx & 3, gg = (idx >> 2) & 7, mp = (idx >> 5) & 15, ss = idx >> 9;
        long long r0 = bm + mp * 16 + gg;
        long long r1 = r0 + 8;
        if (r0 > M - 1) r0 = M - 1;
        if (r1 > M - 1) r1 = M - 1;
        int k0 = ss * 16 + 2 * cc;
        pa0[i] = Ab + (r0 * K + k0) * ES;
        pa1[i] = Ab + (r1 * K + k0) * ES;
    }
    const char* pb0[2];
    const char* pb1[2];
#pragma unroll
    for (int i = 0; i < 2; i++) {
        int idx = tid + i * 256;
        int cc = idx & 3, gg = (idx >> 2) & 7, npr = (idx >> 5) & 7, ss = idx >> 8;
        int n0 = bn + npr * 16 + gg;
        int k0 = ss * 16 + 2 * cc;
        pb0[i] = (const char*)(Wt + (long long)n0 * K + k0);
        pb1[i] = pb0[i] + 8ll * K * 2;
    }

    float acc[4][4][2][4];
#pragma unroll
    for (int i = 0; i < 4; i++)
#pragma unroll
        for (int j = 0; j < 4; j++)
#pragma unroll
            for (int h = 0; h < 2; h++)
#pragma unroll
                for (int q = 0; q < 4; q++) acc[i][j][h][q] = 0.0f;

    // prefetch registers
    uint32_t pfa[16];
    float2 pfa32[16];
    uint32_t pfb[8];

    // ---- prefetch one k-slab into registers ----
#define PREFETCH()                                                            \
    do {                                                                      \
        _Pragma("unroll")                                                     \
        for (int i = 0; i < 4; i++) {                                         \
            if (AF32) {                                                       \
                pfa32[4 * i + 0] = *(const float2*)(pa0[i]);                  \
                pfa32[4 * i + 1] = *(const float2*)(pa1[i]);                  \
                pfa32[4 * i + 2] = *(const float2*)(pa0[i] + 32);             \
                pfa32[4 * i + 3] = *(const float2*)(pa1[i] + 32);             \
                pa0[i] += 128; pa1[i] += 128;                                 \
            } else {                                                          \
                pfa[4 * i + 0] = *(const uint32_t*)(pa0[i]);                  \
                pfa[4 * i + 1] = *(const uint32_t*)(pa1[i]);                  \
                pfa[4 * i + 2] = *(const uint32_t*)(pa0[i] + 16);             \
                pfa[4 * i + 3] = *(const uint32_t*)(pa1[i] + 16);             \
                pa0[i] += 64; pa1[i] += 64;                                   \
            }                                                                 \
        }                                                                     \
        _Pragma("unroll")                                                     \
        for (int i = 0; i < 2; i++) {                                         \
            pfb[4 * i + 0] = *(const uint32_t*)(pb0[i]);                      \
            pfb[4 * i + 1] = *(const uint32_t*)(pb0[i] + 16);                 \
            pfb[4 * i + 2] = *(const uint32_t*)(pb1[i]);                      \
            pfb[4 * i + 3] = *(const uint32_t*)(pb1[i] + 16);                 \
            pb0[i] += 64; pb1[i] += 64;                                       \
        }                                                                     \
    } while (0)

#define STORE_SLAB(buf)                                                       \
    do {                                                                      \
        uint4* As_ = sm + (buf) * 1536;                                       \
        uint4* Bs_ = As_ + 1024;                                              \
        _Pragma("unroll")                                                     \
        for (int i = 0; i < 4; i++) {                                         \
            uint4 v;                                                          \
            if (AF32) {                                                       \
                v.x = packh2(pfa32[4 * i + 0].x, pfa32[4 * i + 0].y);         \
                v.y = packh2(pfa32[4 * i + 1].x, pfa32[4 * i + 1].y);         \
                v.z = packh2(pfa32[4 * i + 2].x, pfa32[4 * i + 2].y);         \
                v.w = packh2(pfa32[4 * i + 3].x, pfa32[4 * i + 3].y);         \
            } else {                                                          \
                v = make_uint4(pfa[4 * i], pfa[4 * i + 1],                    \
                               pfa[4 * i + 2], pfa[4 * i + 3]);               \
            }                                                                 \
            As_[tid + i * 256] = v;                                           \
        }                                                                     \
        _Pragma("unroll")                                                     \
        for (int i = 0; i < 2; i++)                                           \
            Bs_[tid + i * 256] = make_uint4(pfb[4 * i], pfb[4 * i + 1],       \
                                            pfb[4 * i + 2], pfb[4 * i + 3]);  \
    } while (0)

    PREFETCH();

    for (int kt = 0; kt < KT; kt++) {
        const int buf = kt & 1;
        STORE_SLAB(buf);
        __syncthreads();
        if (kt + 1 < KT) PREFETCH();

        const uint4* As = sm + buf * 1536;
        const uint4* Bs = As + 1024;
#pragma unroll
        for (int s = 0; s < 2; s++) {
            uint4 af[4], bf[4];
#pragma unroll
            for (int mt = 0; mt < 4; mt++)
                af[mt] = As[((s * 16 + warp_m * 4 + mt) * 8 + g) * 4 + c];
#pragma unroll
            for (int j = 0; j < 4; j++)
                bf[j] = Bs[((s * 8 + warp_n * 4 + j) * 8 + g) * 4 + c];
#pragma unroll
            for (int mt = 0; mt < 4; mt++)
#pragma unroll
                for (int j = 0; j < 4; j++) {
                    mma_fp16(acc[mt][j][0], af[mt], bf[j].x, bf[j].y);
                    mma_fp16(acc[mt][j][1], af[mt], bf[j].z, bf[j].w);
                }
        }
    }

    // ---- epilogue: bias + sigmoid ----
#pragma unroll
    for (int mt = 0; mt < 4; mt++) {
        long long gr0 = bm + warp_m * 64 + mt * 16 + g;
        long long gr1 = gr0 + 8;
#pragma unroll
        for (int j = 0; j < 4; j++)
#pragma unroll
            for (int h = 0; h < 2; h++) {
                int n = bn + warp_n * 64 + j * 16 + h * 8 + 2 * c;
                float2 bv = *(const float2*)(bias + n);
                float* d = acc[mt][j][h];
                if (gr0 < M) {
                    float s0 = fast_sigmoid(d[0] + bv.x);
                    float s1 = fast_sigmoid(d[1] + bv.y);
                    if (CF32) {
                        *(float2*)((float*)a.C[t] + gr0 * N + n) = make_float2(s0, s1);
                    } else {
                        *(uint32_t*)((__half*)a.C[t] + gr0 * N + n) = packh2(s0, s1);
                    }
                }
                if (gr1 < M) {
                    float s0 = fast_sigmoid(d[2] + bv.x);
                    float s1 = fast_sigmoid(d[3] + bv.y);
                    if (CF32) {
                        *(float2*)((float*)a.C[t] + gr1 * N + n) = make_float2(s0, s1);
                    } else {
                        *(uint32_t*)((__half*)a.C[t] + gr1 * N + n) = packh2(s0, s1);
                    }
                }
            }
    }
#undef PREFETCH
#undef STORE_SLAB
}

// ------------------------- host launcher -----------------------------------
extern "C" void kernel_launch(void* const* d_in, const int* in_sizes, int n_in,
                              void* d_out, int out_size)
{
    (void)n_in; (void)out_size;
    const int din[3] = {64, 128, 256};
    int n[3];
    for (int t = 0; t < 3; t++) n[t] = in_sizes[t] / din[t];

    int tiles[3], tb[4];
    tb[0] = 0;
    for (int t = 0; t < 3; t++) {
        tiles[t] = (n[t] + 255) / 256;
        tb[t + 1] = tb[t] + tiles[t];
    }
    long long padbase[3] = {0, (long long)tb[1] * 256, (long long)tb[2] * 256};
    long long outbase[3] = {0, n[0], (long long)n[0] + n[1]};

    // ---- transpose + fp16-convert all weights ----
    TransArgs ta;
    long long woff[9];
    {
        long long w = 0;
        int tbt = 0;
        for (int t = 0; t < 3; t++) {
            int Ks[3] = {din[t], 512, 512};
            int Ns[3] = {512, 512, 256};
            for (int l = 0; l < 3; l++) {
                int idx = t * 3 + l;
                ta.W[idx] = (const float*)d_in[4 + 6 * t + 2 * l];
                ta.wtoff[idx] = w;
                woff[idx] = w;
                ta.K[idx] = Ks[l];
                ta.N[idx] = Ns[l];
                ta.tbase[idx] = tbt;
                tbt += (Ks[l] / 32) * (Ns[l] / 32);
                w += (long long)Ks[l] * Ns[l];
            }
        }
        ta.tbase[9] = tbt;
        transpose_weights<<<tbt, 256>>>(ta);
    }

    __half* h1 = nullptr; __half* h2 = nullptr;
    cudaGetSymbolAddress((void**)&h1, g_h1);
    cudaGetSymbolAddress((void**)&h2, g_h2);

    const int SMEM = 2 * 1536 * 16;   // 49152 bytes

    // ---- layer 1: x (fp32) -> g_h1 (fp16) ----
    {
        LArgs a;
        a.N = 512;
        for (int t = 0; t < 3; t++) {
            a.A[t] = d_in[t];
            a.C[t] = h1 + padbase[t] * 512;
            a.bias[t] = (const float*)d_in[5 + 6 * t];
            a.wt[t] = woff[t * 3 + 0];
            a.M[t] = n[t];
            a.K[t] = din[t];
        }
        for (int i = 0; i < 4; i++) a.tb[i] = tb[i];
        dim3 grid(4, tb[3]);
        mlp_layer<true, false><<<grid, 256, SMEM>>>(a);
    }
    // ---- layer 2: g_h1 -> g_h2 ----
    {
        LArgs a;
        a.N = 512;
        for (int t = 0; t < 3; t++) {
            a.A[t] = h1 + padbase[t] * 512;
            a.C[t] = h2 + padbase[t] * 512;
            a.bias[t] = (const float*)d_in[7 + 6 * t];
            a.wt[t] = woff[t * 3 + 1];
            a.M[t] = n[t];
            a.K[t] = 512;
        }
        for (int i = 0; i < 4; i++) a.tb[i] = tb[i];
        dim3 grid(4, tb[3]);
        mlp_layer<false, false><<<grid, 256, SMEM>>>(a);
    }
    // ---- layer 3: g_h2 -> out (fp32, packed) ----
    {
        LArgs a;
        a.N = 256;
        for (int t = 0; t < 3; t++) {
            a.A[t] = h2 + padbase[t] * 512;
            a.C[t] = (float*)d_out + outbase[t] * 256;
            a.bias[t] = (const float*)d_in[9 + 6 * t];
            a.wt[t] = woff[t * 3 + 2];
            a.M[t] = n[t];
            a.K[t] = 512;
        }
        for (int i = 0; i < 4; i++) a.tb[i] = tb[i];
        dim3 grid(2, tb[3]);
        mlp_layer<false, true><<<grid, 256, SMEM>>>(a);
    }
}

// round 7
// speedup vs baseline: 7.7352x; 1.8858x over previous
#include <cuda_runtime.h>
#include <cuda_fp16.h>
#include <cstdint>

// ---------------------------------------------------------------------------
// EncoderByType (GB300, compute_103 baseline): fp16 m16n8k16 mma.sync GEMM,
// cp.async 3-stage pipeline, ldmatrix fragments, 2 CTAs/SM (128 thr, 96KB).
// CTA tile 128x128x64, warp tile 64x64. All activations fp16, padded to
// 128-row tiles (no bounds checks in mainloop). 1 transpose + 3 convert +
// 3 layer launches.
// ---------------------------------------------------------------------------

__device__ __half g_x [32014336];          // padded fp16 inputs (per-type)
__device__ __half g_h1[240128ll * 512];
__device__ __half g_h2[240128ll * 512];
__device__ __half g_Wt[1409024];           // 9 weights, [N,K] fp16

// ------------------------- helpers -----------------------------------------
__device__ __forceinline__ uint32_t smem_u32(const void* p) {
    uint32_t a;
    asm("{ .reg .u64 t; cvta.to.shared.u64 t, %1; cvt.u32.u64 %0, t; }"
        : "=r"(a) : "l"(p));
    return a;
}

__device__ __forceinline__ float fast_sigmoid(float x) {
    float t;
    asm("tanh.approx.f32 %0, %1;" : "=f"(t) : "f"(0.5f * x));
    return fmaf(0.5f, t, 0.5f);
}

__device__ __forceinline__ uint32_t packh2(float lo, float hi) {
    __half2 h = __floats2half2_rn(lo, hi);
    return *reinterpret_cast<uint32_t*>(&h);
}

__device__ __forceinline__ void mma_fp16(float* d, const uint4& a,
                                         uint32_t b0, uint32_t b1) {
    asm volatile(
        "mma.sync.aligned.m16n8k16.row.col.f32.f16.f16.f32 "
        "{%0,%1,%2,%3}, {%4,%5,%6,%7}, {%8,%9}, {%0,%1,%2,%3};"
        : "+f"(d[0]), "+f"(d[1]), "+f"(d[2]), "+f"(d[3])
        : "r"(a.x), "r"(a.y), "r"(a.z), "r"(a.w), "r"(b0), "r"(b1));
}

__device__ __forceinline__ void ldsm4(uint4& d, uint32_t addr) {
    asm volatile(
        "ldmatrix.sync.aligned.m8n8.x4.shared.b16 {%0,%1,%2,%3}, [%4];"
        : "=r"(d.x), "=r"(d.y), "=r"(d.z), "=r"(d.w) : "r"(addr));
}

#define CP_ASYNC16(dst, src) \
    asm volatile("cp.async.cg.shared.global [%0], [%1], 16;" :: "r"(dst), "l"(src))
#define CP_COMMIT() asm volatile("cp.async.commit_group;" ::: "memory")
#define CP_WAIT(n)  asm volatile("cp.async.wait_group %0;" :: "n"(n) : "memory")

// ------------------------- weight transpose+convert ------------------------
struct TransArgs {
    const float* W[9];
    long long wtoff[9];
    int K[9];
    int N[9];
    int tbase[10];
};

__global__ void __launch_bounds__(256)
transpose_weights(TransArgs a) {
    int m = 0;
    while ((int)blockIdx.x >= a.tbase[m + 1]) m++;
    int t = blockIdx.x - a.tbase[m];
    int Km = a.K[m], Nm = a.N[m];
    int tilesN = Nm >> 5;
    int tk = t / tilesN, tn = t % tilesN;

    __shared__ float tile[32][33];
    int tx = threadIdx.x & 31, ty0 = threadIdx.x >> 5;
    const float* W = a.W[m];
#pragma unroll
    for (int i = 0; i < 4; i++) {
        int ty = ty0 + i * 8;
        tile[ty][tx] = W[(long long)(tk * 32 + ty) * Nm + tn * 32 + tx];
    }
    __syncthreads();
    __half* Wt = g_Wt + a.wtoff[m];
#pragma unroll
    for (int i = 0; i < 4; i++) {
        int ty = ty0 + i * 8;
        Wt[(long long)(tn * 32 + ty) * Km + tk * 32 + tx] = __float2half(tile[tx][ty]);
    }
}

// ------------------------- input convert (fp32 -> fp16) --------------------
__global__ void __launch_bounds__(128)
cvt_fp16(const float* __restrict__ s, __half* __restrict__ d, int n4) {
    int i = blockIdx.x * 128 + threadIdx.x;
    if (i < n4) {
        float4 v = ((const float4*)s)[i];
        uint2 o;
        o.x = packh2(v.x, v.y);
        o.y = packh2(v.z, v.w);
        ((uint2*)d)[i] = o;
    }
}

// ------------------------- fused layer kernel ------------------------------
// Grid: (N/128, sum_tiles). CTA 128 threads = 4 warps (2m x 2n), warp 64x64.
// Smem: 3 stages x (A 16KB + B 16KB) = 96KB. BK = 64 halfs (128B rows),
// XOR swizzle: 16B chunk c stored at c ^ (row & 7).
struct LArgs {
    const __half* A[3];
    void* C[3];
    const float* bias[3];
    const __half* Wt[3];
    int M[3], K[3];
    int tb[4];
    int N;
};

template <bool CF32>
__global__ void __launch_bounds__(128)
mlp_layer(LArgs a)
{
    extern __shared__ char smem[];
    const int t = ((int)blockIdx.y >= a.tb[1]) + ((int)blockIdx.y >= a.tb[2]);
    const int K = a.K[t];
    const int N = a.N;
    const long long bm = (long long)((int)blockIdx.y - a.tb[t]) * 128;
    const int bn = blockIdx.x * 128;
    const __half* Ah = a.A[t];
    const __half* Wt = a.Wt[t];
    const int KT = K >> 6;

    const int tid = threadIdx.x;
    const int lane = tid & 31;
    const int wid = tid >> 5;
    const int warp_m = wid >> 1;
    const int warp_n = wid & 1;

    const uint32_t sb = smem_u32(smem);

    // ---- cp.async source/dst maps: 1024 16B-chunks each for A and B ----
    const int crow = tid >> 3;         // 0..15 (+ i*16)
    const int cchk = tid & 7;          // 16B chunk in 128B row
    const __half* pA = Ah + (bm + crow) * (long long)K + cchk * 8;
    const __half* pB = Wt + (long long)(bn + crow) * K + cchk * 8;
    const uint32_t swz = (uint32_t)((cchk ^ (crow & 7)) * 16);
    const uint32_t dA = sb + crow * 128 + swz;
    const uint32_t dB = sb + 16384 + crow * 128 + swz;
    const long long rstep = 16ll * K;  // halfs per 16 rows

    // ---- ldmatrix address bases ----
    const int l15 = lane & 15;
    const int ahi = lane >> 4;                     // k8-half select
    const uint32_t aX = (uint32_t)(lane & 7);
    const uint32_t aBase = sb + (uint32_t)(warp_m * 64 + l15) * 128;
    const int bn_l = warp_n * 64 + ((lane >> 4) << 3) + (lane & 7);
    const int bhi = (lane >> 3) & 1;
    const uint32_t bX = (uint32_t)(lane & 7);
    const uint32_t bBase = sb + 16384 + (uint32_t)bn_l * 128;

    float acc[4][8][4];
#pragma unroll
    for (int i = 0; i < 4; i++)
#pragma unroll
        for (int j = 0; j < 8; j++)
#pragma unroll
            for (int q = 0; q < 4; q++) acc[i][j][q] = 0.0f;

#define ISSUE(kt, slot)                                                      \
    do {                                                                     \
        const __half* sA_ = pA + (kt) * 64;                                  \
        const __half* sB_ = pB + (kt) * 64;                                  \
        uint32_t oA_ = dA + (slot) * 32768u;                                 \
        uint32_t oB_ = dB + (slot) * 32768u;                                 \
        _Pragma("unroll")                                                    \
        for (int i = 0; i < 8; i++)                                          \
            CP_ASYNC16(oA_ + i * 2048u, sA_ + i * rstep);                    \
        _Pragma("unroll")                                                    \
        for (int i = 0; i < 8; i++)                                          \
            CP_ASYNC16(oB_ + i * 2048u, sB_ + i * rstep);                    \
    } while (0)

    // ---- prologue: fill 2 stages ----
    if (0 < KT) ISSUE(0, 0);
    CP_COMMIT();
    if (1 < KT) ISSUE(1, 1);
    CP_COMMIT();

    int pf = 2;
    for (int kt = 0; kt < KT; kt++) {
        CP_WAIT(1);
        __syncthreads();
        // issue next stage (into the slot consumed at kt-1 -> all warps past it)
        if (pf < KT) {
            int slot = pf - (pf / 3) * 3;
            ISSUE(pf, slot);
        }
        CP_COMMIT();
        pf++;

        const int cur = kt - (kt / 3) * 3;
        const uint32_t aS = aBase + cur * 32768u;
        const uint32_t bS = bBase + cur * 32768u;
#pragma unroll
        for (int s = 0; s < 4; s++) {
            uint4 af[4];
#pragma unroll
            for (int mt = 0; mt < 4; mt++)
                ldsm4(af[mt], aS + mt * 2048u + ((((uint32_t)(2 * s + ahi)) ^ aX) << 4));
            uint4 bf[4];
#pragma unroll
            for (int ng = 0; ng < 4; ng++)
                ldsm4(bf[ng], bS + ng * 2048u + ((((uint32_t)(2 * s + bhi)) ^ bX) << 4));
#pragma unroll
            for (int mt = 0; mt < 4; mt++)
#pragma unroll
                for (int ng = 0; ng < 4; ng++) {
                    mma_fp16(acc[mt][2 * ng + 0], af[mt], bf[ng].x, bf[ng].y);
                    mma_fp16(acc[mt][2 * ng + 1], af[mt], bf[ng].z, bf[ng].w);
                }
        }
    }
#undef ISSUE

    // ---- epilogue: bias + sigmoid ----
    const float* bias = a.bias[t];
    const int M = a.M[t];
#pragma unroll
    for (int mt = 0; mt < 4; mt++) {
        long long r0 = bm + warp_m * 64 + mt * 16 + (lane >> 2);
        long long r1 = r0 + 8;
#pragma unroll
        for (int np = 0; np < 8; np++) {
            int n = bn + warp_n * 64 + np * 8 + 2 * (lane & 3);
            float2 bv = *(const float2*)(bias + n);
            float* d = acc[mt][np];
            float s0 = fast_sigmoid(d[0] + bv.x);
            float s1 = fast_sigmoid(d[1] + bv.y);
            float s2 = fast_sigmoid(d[2] + bv.x);
            float s3 = fast_sigmoid(d[3] + bv.y);
            if (CF32) {
                float* C = (float*)a.C[t];
                if (r0 < M) *(float2*)(C + r0 * N + n) = make_float2(s0, s1);
                if (r1 < M) *(float2*)(C + r1 * N + n) = make_float2(s2, s3);
            } else {
                __half* C = (__half*)a.C[t];
                *(uint32_t*)(C + r0 * N + n) = packh2(s0, s1);
                *(uint32_t*)(C + r1 * N + n) = packh2(s2, s3);
            }
        }
    }
}

// ------------------------- host launcher -----------------------------------
extern "C" void kernel_launch(void* const* d_in, const int* in_sizes, int n_in,
                              void* d_out, int out_size)
{
    (void)n_in; (void)out_size;
    const int din[3] = {64, 128, 256};
    int n[3];
    for (int t = 0; t < 3; t++) n[t] = in_sizes[t] / din[t];

    int tiles[3], tb[4];
    tb[0] = 0;
    for (int t = 0; t < 3; t++) {
        tiles[t] = (n[t] + 127) / 128;
        tb[t + 1] = tb[t] + tiles[t];
    }
    long long padrows[3] = {(long long)tiles[0] * 128, (long long)tiles[1] * 128,
                            (long long)tiles[2] * 128};
    long long hb[3] = {0, padrows[0], padrows[0] + padrows[1]};
    long long xoff[3] = {0, padrows[0] * din[0],
                         padrows[0] * din[0] + padrows[1] * din[1]};
    long long outbase[3] = {0, n[0], (long long)n[0] + n[1]};

    const int SMEM = 3 * 32768;   // 98304
    static int attr_done = 0;
    if (!attr_done) {
        cudaFuncSetAttribute(mlp_layer<false>,
                             cudaFuncAttributeMaxDynamicSharedMemorySize, SMEM);
        cudaFuncSetAttribute(mlp_layer<true>,
                             cudaFuncAttributeMaxDynamicSharedMemorySize, SMEM);
        attr_done = 1;
    }

    // ---- transpose + fp16-convert all weights ----
    TransArgs ta;
    long long woff[9];
    {
        long long w = 0;
        int tbt = 0;
        for (int t = 0; t < 3; t++) {
            int Ks[3] = {din[t], 512, 512};
            int Ns[3] = {512, 512, 256};
            for (int l = 0; l < 3; l++) {
                int idx = t * 3 + l;
                ta.W[idx] = (const float*)d_in[4 + 6 * t + 2 * l];
                ta.wtoff[idx] = w;
                woff[idx] = w;
                ta.K[idx] = Ks[l];
                ta.N[idx] = Ns[l];
                ta.tbase[idx] = tbt;
                tbt += (Ks[l] / 32) * (Ns[l] / 32);
                w += (long long)Ks[l] * Ns[l];
            }
        }
        ta.tbase[9] = tbt;
        transpose_weights<<<tbt, 256>>>(ta);
    }

    __half *xh, *h1, *h2, *wt;
    cudaGetSymbolAddress((void**)&xh, g_x);
    cudaGetSymbolAddress((void**)&h1, g_h1);
    cudaGetSymbolAddress((void**)&h2, g_h2);
    cudaGetSymbolAddress((void**)&wt, g_Wt);

    // ---- convert inputs to padded fp16 ----
    for (int t = 0; t < 3; t++) {
        int n4 = n[t] * din[t] / 4;
        cvt_fp16<<<(n4 + 127) / 128, 128>>>((const float*)d_in[t], xh + xoff[t], n4);
    }

    // ---- layer launches ----
    LArgs a;
    for (int i = 0; i < 4; i++) a.tb[i] = tb[i];

    // layer 1
    a.N = 512;
    for (int t = 0; t < 3; t++) {
        a.A[t] = xh + xoff[t];
        a.C[t] = h1 + hb[t] * 512;
        a.bias[t] = (const float*)d_in[5 + 6 * t];
        a.Wt[t] = wt + woff[t * 3 + 0];
        a.M[t] = n[t];
        a.K[t] = din[t];
    }
    mlp_layer<false><<<dim3(4, tb[3]), 128, SMEM>>>(a);

    // layer 2
    for (int t = 0; t < 3; t++) {
        a.A[t] = h1 + hb[t] * 512;
        a.C[t] = h2 + hb[t] * 512;
        a.bias[t] = (const float*)d_in[7 + 6 * t];
        a.Wt[t] = wt + woff[t * 3 + 1];
        a.M[t] = n[t];
        a.K[t] = 512;
    }
    mlp_layer<false><<<dim3(4, tb[3]), 128, SMEM>>>(a);

    // layer 3
    a.N = 256;
    for (int t = 0; t < 3; t++) {
        a.A[t] = h2 + hb[t] * 512;
        a.C[t] = (float*)d_out + outbase[t] * 256;
        a.bias[t] = (const float*)d_in[9 + 6 * t];
        a.Wt[t] = wt + woff[t * 3 + 2];
        a.M[t] = n[t];
        a.K[t] = 512;
    }
    mlp_layer<true><<<dim3(2, tb[3]), 128, SMEM>>>(a);
}

// round 8
// speedup vs baseline: 7.7528x; 1.0023x over previous
#include <cuda_runtime.h>
#include <cuda_fp16.h>
#include <cstdint>

// ---------------------------------------------------------------------------
// EncoderByType (GB300, compute_103 baseline): fp16 m16n8k16 mma.sync GEMM,
// cp.async 3-stage pipeline, ldmatrix fragments, 2 CTAs/SM (128 thr, 96KB).
// CTA tile 128x128x64, warp tile 64x64. All activations fp16, padded to
// 128-row tiles (no bounds checks in mainloop). 1 transpose + 3 convert +
// 3 layer launches.
// ---------------------------------------------------------------------------

__device__ __half g_x [32014336];          // padded fp16 inputs (per-type)
__device__ __half g_h1[240128ll * 512];
__device__ __half g_h2[240128ll * 512];
__device__ __half g_Wt[1409024];           // 9 weights, [N,K] fp16

// ------------------------- helpers -----------------------------------------
__device__ __forceinline__ uint32_t smem_u32(const void* p) {
    uint32_t a;
    asm("{ .reg .u64 t; cvta.to.shared.u64 t, %1; cvt.u32.u64 %0, t; }"
        : "=r"(a) : "l"(p));
    return a;
}

__device__ __forceinline__ float fast_sigmoid(float x) {
    float t;
    asm("tanh.approx.f32 %0, %1;" : "=f"(t) : "f"(0.5f * x));
    return fmaf(0.5f, t, 0.5f);
}

__device__ __forceinline__ uint32_t packh2(float lo, float hi) {
    __half2 h = __floats2half2_rn(lo, hi);
    return *reinterpret_cast<uint32_t*>(&h);
}

__device__ __forceinline__ void mma_fp16(float* d, const uint4& a,
                                         uint32_t b0, uint32_t b1) {
    asm volatile(
        "mma.sync.aligned.m16n8k16.row.col.f32.f16.f16.f32 "
        "{%0,%1,%2,%3}, {%4,%5,%6,%7}, {%8,%9}, {%0,%1,%2,%3};"
        : "+f"(d[0]), "+f"(d[1]), "+f"(d[2]), "+f"(d[3])
        : "r"(a.x), "r"(a.y), "r"(a.z), "r"(a.w), "r"(b0), "r"(b1));
}

__device__ __forceinline__ void ldsm4(uint4& d, uint32_t addr) {
    asm volatile(
        "ldmatrix.sync.aligned.m8n8.x4.shared.b16 {%0,%1,%2,%3}, [%4];"
        : "=r"(d.x), "=r"(d.y), "=r"(d.z), "=r"(d.w) : "r"(addr));
}

#define CP_ASYNC16(dst, src) \
    asm volatile("cp.async.cg.shared.global [%0], [%1], 16;" :: "r"(dst), "l"(src))
#define CP_COMMIT() asm volatile("cp.async.commit_group;" ::: "memory")
#define CP_WAIT(n)  asm volatile("cp.async.wait_group %0;" :: "n"(n) : "memory")

// ------------------------- weight transpose+convert ------------------------
struct TransArgs {
    const float* W[9];
    long long wtoff[9];
    int K[9];
    int N[9];
    int tbase[10];
};

__global__ void __launch_bounds__(256)
transpose_weights(TransArgs a) {
    int m = 0;
    while ((int)blockIdx.x >= a.tbase[m + 1]) m++;
    int t = blockIdx.x - a.tbase[m];
    int Km = a.K[m], Nm = a.N[m];
    int tilesN = Nm >> 5;
    int tk = t / tilesN, tn = t % tilesN;

    __shared__ float tile[32][33];
    int tx = threadIdx.x & 31, ty0 = threadIdx.x >> 5;
    const float* W = a.W[m];
#pragma unroll
    for (int i = 0; i < 4; i++) {
        int ty = ty0 + i * 8;
        tile[ty][tx] = W[(long long)(tk * 32 + ty) * Nm + tn * 32 + tx];
    }
    __syncthreads();
    __half* Wt = g_Wt + a.wtoff[m];
#pragma unroll
    for (int i = 0; i < 4; i++) {
        int ty = ty0 + i * 8;
        Wt[(long long)(tn * 32 + ty) * Km + tk * 32 + tx] = __float2half(tile[tx][ty]);
    }
}

// ------------------------- input convert (fp32 -> fp16) --------------------
__global__ void __launch_bounds__(128)
cvt_fp16(const float* __restrict__ s, __half* __restrict__ d, int n4) {
    int i = blockIdx.x * 128 + threadIdx.x;
    if (i < n4) {
        float4 v = ((const float4*)s)[i];
        uint2 o;
        o.x = packh2(v.x, v.y);
        o.y = packh2(v.z, v.w);
        ((uint2*)d)[i] = o;
    }
}

// ------------------------- fused layer kernel ------------------------------
// Grid: (N/128, sum_tiles). CTA 128 threads = 4 warps (2m x 2n), warp 64x64.
// Smem: 3 stages x (A 16KB + B 16KB) = 96KB. BK = 64 halfs (128B rows),
// XOR swizzle: 16B chunk c stored at c ^ (row & 7).
struct LArgs {
    const __half* A[3];
    void* C[3];
    const float* bias[3];
    const __half* Wt[3];
    int M[3], K[3];
    int tb[4];
    int N;
};

template <bool CF32>
__global__ void __launch_bounds__(128)
mlp_layer(LArgs a)
{
    extern __shared__ char smem[];
    const int t = ((int)blockIdx.y >= a.tb[1]) + ((int)blockIdx.y >= a.tb[2]);
    const int K = a.K[t];
    const int N = a.N;
    const long long bm = (long long)((int)blockIdx.y - a.tb[t]) * 128;
    const int bn = blockIdx.x * 128;
    const __half* Ah = a.A[t];
    const __half* Wt = a.Wt[t];
    const int KT = K >> 6;

    const int tid = threadIdx.x;
    const int lane = tid & 31;
    const int wid = tid >> 5;
    const int warp_m = wid >> 1;
    const int warp_n = wid & 1;

    const uint32_t sb = smem_u32(smem);

    // ---- cp.async source/dst maps: 1024 16B-chunks each for A and B ----
    const int crow = tid >> 3;         // 0..15 (+ i*16)
    const int cchk = tid & 7;          // 16B chunk in 128B row
    const __half* pA = Ah + (bm + crow) * (long long)K + cchk * 8;
    const __half* pB = Wt + (long long)(bn + crow) * K + cchk * 8;
    const uint32_t swz = (uint32_t)((cchk ^ (crow & 7)) * 16);
    const uint32_t dA = sb + crow * 128 + swz;
    const uint32_t dB = sb + 16384 + crow * 128 + swz;
    const long long rstep = 16ll * K;  // halfs per 16 rows

    // ---- ldmatrix address bases ----
    const int l15 = lane & 15;
    const int ahi = lane >> 4;                     // k8-half select
    const uint32_t aX = (uint32_t)(lane & 7);
    const uint32_t aBase = sb + (uint32_t)(warp_m * 64 + l15) * 128;
    const int bn_l = warp_n * 64 + ((lane >> 4) << 3) + (lane & 7);
    const int bhi = (lane >> 3) & 1;
    const uint32_t bX = (uint32_t)(lane & 7);
    const uint32_t bBase = sb + 16384 + (uint32_t)bn_l * 128;

    float acc[4][8][4];
#pragma unroll
    for (int i = 0; i < 4; i++)
#pragma unroll
        for (int j = 0; j < 8; j++)
#pragma unroll
            for (int q = 0; q < 4; q++) acc[i][j][q] = 0.0f;

#define ISSUE(kt, slot)                                                      \
    do {                                                                     \
        const __half* sA_ = pA + (kt) * 64;                                  \
        const __half* sB_ = pB + (kt) * 64;                                  \
        uint32_t oA_ = dA + (slot) * 32768u;                                 \
        uint32_t oB_ = dB + (slot) * 32768u;                                 \
        _Pragma("unroll")                                                    \
        for (int i = 0; i < 8; i++)                                          \
            CP_ASYNC16(oA_ + i * 2048u, sA_ + i * rstep);                    \
        _Pragma("unroll")                                                    \
        for (int i = 0; i < 8; i++)                                          \
            CP_ASYNC16(oB_ + i * 2048u, sB_ + i * rstep);                    \
    } while (0)

    // ---- prologue: fill 2 stages ----
    if (0 < KT) ISSUE(0, 0);
    CP_COMMIT();
    if (1 < KT) ISSUE(1, 1);
    CP_COMMIT();

    int pf = 2;
    for (int kt = 0; kt < KT; kt++) {
        CP_WAIT(1);
        __syncthreads();
        // issue next stage (into the slot consumed at kt-1 -> all warps past it)
        if (pf < KT) {
            int slot = pf - (pf / 3) * 3;
            ISSUE(pf, slot);
        }
        CP_COMMIT();
        pf++;

        const int cur = kt - (kt / 3) * 3;
        const uint32_t aS = aBase + cur * 32768u;
        const uint32_t bS = bBase + cur * 32768u;
#pragma unroll
        for (int s = 0; s < 4; s++) {
            uint4 af[4];
#pragma unroll
            for (int mt = 0; mt < 4; mt++)
                ldsm4(af[mt], aS + mt * 2048u + ((((uint32_t)(2 * s + ahi)) ^ aX) << 4));
            uint4 bf[4];
#pragma unroll
            for (int ng = 0; ng < 4; ng++)
                ldsm4(bf[ng], bS + ng * 2048u + ((((uint32_t)(2 * s + bhi)) ^ bX) << 4));
#pragma unroll
            for (int mt = 0; mt < 4; mt++)
#pragma unroll
                for (int ng = 0; ng < 4; ng++) {
                    mma_fp16(acc[mt][2 * ng + 0], af[mt], bf[ng].x, bf[ng].y);
                    mma_fp16(acc[mt][2 * ng + 1], af[mt], bf[ng].z, bf[ng].w);
                }
        }
    }
#undef ISSUE

    // ---- epilogue: bias + sigmoid ----
    const float* bias = a.bias[t];
    const int M = a.M[t];
#pragma unroll
    for (int mt = 0; mt < 4; mt++) {
        long long r0 = bm + warp_m * 64 + mt * 16 + (lane >> 2);
        long long r1 = r0 + 8;
#pragma unroll
        for (int np = 0; np < 8; np++) {
            int n = bn + warp_n * 64 + np * 8 + 2 * (lane & 3);
            float2 bv = *(const float2*)(bias + n);
            float* d = acc[mt][np];
            float s0 = fast_sigmoid(d[0] + bv.x);
            float s1 = fast_sigmoid(d[1] + bv.y);
            float s2 = fast_sigmoid(d[2] + bv.x);
            float s3 = fast_sigmoid(d[3] + bv.y);
            if (CF32) {
                float* C = (float*)a.C[t];
                if (r0 < M) *(float2*)(C + r0 * N + n) = make_float2(s0, s1);
                if (r1 < M) *(float2*)(C + r1 * N + n) = make_float2(s2, s3);
            } else {
                __half* C = (__half*)a.C[t];
                *(uint32_t*)(C + r0 * N + n) = packh2(s0, s1);
                *(uint32_t*)(C + r1 * N + n) = packh2(s2, s3);
            }
        }
    }
}

// ------------------------- host launcher -----------------------------------
extern "C" void kernel_launch(void* const* d_in, const int* in_sizes, int n_in,
                              void* d_out, int out_size)
{
    (void)n_in; (void)out_size;
    const int din[3] = {64, 128, 256};
    int n[3];
    for (int t = 0; t < 3; t++) n[t] = in_sizes[t] / din[t];

    int tiles[3], tb[4];
    tb[0] = 0;
    for (int t = 0; t < 3; t++) {
        tiles[t] = (n[t] + 127) / 128;
        tb[t + 1] = tb[t] + tiles[t];
    }
    long long padrows[3] = {(long long)tiles[0] * 128, (long long)tiles[1] * 128,
                            (long long)tiles[2] * 128};
    long long hb[3] = {0, padrows[0], padrows[0] + padrows[1]};
    long long xoff[3] = {0, padrows[0] * din[0],
                         padrows[0] * din[0] + padrows[1] * din[1]};
    long long outbase[3] = {0, n[0], (long long)n[0] + n[1]};

    const int SMEM = 3 * 32768;   // 98304
    static int attr_done = 0;
    if (!attr_done) {
        cudaFuncSetAttribute(mlp_layer<false>,
                             cudaFuncAttributeMaxDynamicSharedMemorySize, SMEM);
        cudaFuncSetAttribute(mlp_layer<true>,
                             cudaFuncAttributeMaxDynamicSharedMemorySize, SMEM);
        attr_done = 1;
    }

    // ---- transpose + fp16-convert all weights ----
    TransArgs ta;
    long long woff[9];
    {
        long long w = 0;
        int tbt = 0;
        for (int t = 0; t < 3; t++) {
            int Ks[3] = {din[t], 512, 512};
            int Ns[3] = {512, 512, 256};
            for (int l = 0; l < 3; l++) {
                int idx = t * 3 + l;
                ta.W[idx] = (const float*)d_in[4 + 6 * t + 2 * l];
                ta.wtoff[idx] = w;
                woff[idx] = w;
                ta.K[idx] = Ks[l];
                ta.N[idx] = Ns[l];
                ta.tbase[idx] = tbt;
                tbt += (Ks[l] / 32) * (Ns[l] / 32);
                w += (long long)Ks[l] * Ns[l];
            }
        }
        ta.tbase[9] = tbt;
        transpose_weights<<<tbt, 256>>>(ta);
    }

    __half *xh, *h1, *h2, *wt;
    cudaGetSymbolAddress((void**)&xh, g_x);
    cudaGetSymbolAddress((void**)&h1, g_h1);
    cudaGetSymbolAddress((void**)&h2, g_h2);
    cudaGetSymbolAddress((void**)&wt, g_Wt);

    // ---- convert inputs to padded fp16 ----
    for (int t = 0; t < 3; t++) {
        int n4 = n[t] * din[t] / 4;
        cvt_fp16<<<(n4 + 127) / 128, 128>>>((const float*)d_in[t], xh + xoff[t], n4);
    }

    // ---- layer launches ----
    LArgs a;
    for (int i = 0; i < 4; i++) a.tb[i] = tb[i];

    // layer 1
    a.N = 512;
    for (int t = 0; t < 3; t++) {
        a.A[t] = xh + xoff[t];
        a.C[t] = h1 + hb[t] * 512;
        a.bias[t] = (const float*)d_in[5 + 6 * t];
        a.Wt[t] = wt + woff[t * 3 + 0];
        a.M[t] = n[t];
        a.K[t] = din[t];
    }
    mlp_layer<false><<<dim3(4, tb[3]), 128, SMEM>>>(a);

    // layer 2
    for (int t = 0; t < 3; t++) {
        a.A[t] = h1 + hb[t] * 512;
        a.C[t] = h2 + hb[t] * 512;
        a.bias[t] = (const float*)d_in[7 + 6 * t];
        a.Wt[t] = wt + woff[t * 3 + 1];
        a.M[t] = n[t];
        a.K[t] = 512;
    }
    mlp_layer<false><<<dim3(4, tb[3]), 128, SMEM>>>(a);

    // layer 3
    a.N = 256;
    for (int t = 0; t < 3; t++) {
        a.A[t] = h2 + hb[t] * 512;
        a.C[t] = (float*)d_out + outbase[t] * 256;
        a.bias[t] = (const float*)d_in[9 + 6 * t];
        a.Wt[t] = wt + woff[t * 3 + 2];
        a.M[t] = n[t];
        a.K[t] = 512;
    }
    mlp_layer<true><<<dim3(2, tb[3]), 128, SMEM>>>(a);
}